// round 4
// baseline (speedup 1.0000x reference)
#include <cuda_runtime.h>

#define NN 20000
#define EE 320000
#define FF 512
#define HH 8
#define DD 64
#define HD 512           // HH*DD
#define LRELU 0.2f
#define EPSV 1e-16f

// ---------------- scratch (static device globals; no allocs) ----------------
__device__ float g_he[NN * HD];          // [n][h*64+d]
__device__ float g_hr[NN * HD];
__device__ float g_Wc[2][FF * HD];       // repacked weights [f][h*64+d]
__device__ float g_sS[NN * HH];
__device__ float g_sD[NN * HH];
__device__ float g_pD[NN * HH];
__device__ int   g_deg[NN];
__device__ int   g_off[NN + 1];
__device__ int   g_cur[NN];
__device__ int   g_srcs[EE];
__device__ int   g_dsts[EE];
__device__ float g_att[HH * EE];         // scores -> exp -> normalized att, [h][p]
__device__ int   g_is64;                 // edge_index dtype flag

// ---------------- dtype probe: int64 vs int32 edge_index -------------------
// int64 nonneg < 2^31  => every odd 32-bit word (high half) is 0.
// int32 random ids     => odd words are node ids, essentially never all zero.
__global__ void detect_k(const int* __restrict__ w) {
    if (threadIdx.x == 0 && blockIdx.x == 0) {
        int ornz = 0;
        for (int i = 1; i < 256; i += 2) ornz |= w[i];
        g_is64 = (ornz == 0) ? 1 : 0;
    }
}

__device__ __forceinline__ int load_idx(const void* ei, int which, int e) {
    if (g_is64) return (int)((const long long*)ei)[(long)which * EE + e];
    return ((const int*)ei)[which * EE + e];
}

// ---------------- weight repack: W[h][f][d] -> Wc[f][h*64+d] ----------------
__global__ void prep_w(const float* __restrict__ We, const float* __restrict__ Wr) {
    int idx = blockIdx.x * blockDim.x + threadIdx.x;
    if (idx >= 2 * FF * HD) return;
    int which = idx / (FF * HD);
    int rem = idx - which * (FF * HD);
    int f = rem >> 9;
    int c = rem & 511;
    int h = c >> 6;
    int d = c & 63;
    const float* W = which ? Wr : We;
    g_Wc[which][f * HD + c] = W[h * (FF * DD) + f * DD + d];
}

// ---------------- SGEMM: C[20000x512] = x[20000x512] @ Wc[512x512] ----------
__global__ __launch_bounds__(256) void sgemm(const float* __restrict__ A) {
    int which = blockIdx.z;
    const float* __restrict__ B = g_Wc[which];
    float* __restrict__ C = which ? g_hr : g_he;

    __shared__ float As[8][132];   // padded to kill bank conflicts
    __shared__ float Bs[8][128];

    int tid = threadIdx.x;
    int tx = tid & 15, ty = tid >> 4;
    int mBase = blockIdx.x * 128, nBase = blockIdx.y * 128;
    int aRow = tid >> 1, aCol = (tid & 1) * 4;
    int bRow = tid >> 5, bCol = (tid & 31) * 4;

    float acc[8][8];
#pragma unroll
    for (int i = 0; i < 8; i++)
#pragma unroll
        for (int j = 0; j < 8; j++) acc[i][j] = 0.f;

    int gm_a = mBase + aRow;
    bool arow_ok = (gm_a < NN);

    for (int k0 = 0; k0 < FF; k0 += 8) {
        float4 av = make_float4(0.f, 0.f, 0.f, 0.f);
        if (arow_ok) av = *(const float4*)(A + (long)gm_a * FF + k0 + aCol);
        As[aCol + 0][aRow] = av.x;
        As[aCol + 1][aRow] = av.y;
        As[aCol + 2][aRow] = av.z;
        As[aCol + 3][aRow] = av.w;

        float4 bv = *(const float4*)(B + (k0 + bRow) * HD + nBase + bCol);
        *(float4*)&Bs[bRow][bCol] = bv;
        __syncthreads();

#pragma unroll
        for (int kk = 0; kk < 8; kk++) {
            float4 a0 = *(const float4*)&As[kk][ty * 8];
            float4 a1 = *(const float4*)&As[kk][ty * 8 + 4];
            float4 b0 = *(const float4*)&Bs[kk][tx * 8];
            float4 b1 = *(const float4*)&Bs[kk][tx * 8 + 4];
            float ar[8] = {a0.x, a0.y, a0.z, a0.w, a1.x, a1.y, a1.z, a1.w};
            float br[8] = {b0.x, b0.y, b0.z, b0.w, b1.x, b1.y, b1.z, b1.w};
#pragma unroll
            for (int i = 0; i < 8; i++)
#pragma unroll
                for (int j = 0; j < 8; j++) acc[i][j] = fmaf(ar[i], br[j], acc[i][j]);
        }
        __syncthreads();
    }

#pragma unroll
    for (int i = 0; i < 8; i++) {
        int gm = mBase + ty * 8 + i;
        if (gm < NN) {
            float* Cr = C + (long)gm * HD + nBase + tx * 8;
            float4 c0 = make_float4(acc[i][0], acc[i][1], acc[i][2], acc[i][3]);
            float4 c1 = make_float4(acc[i][4], acc[i][5], acc[i][6], acc[i][7]);
            *(float4*)Cr = c0;
            *(float4*)(Cr + 4) = c1;
        }
    }
}

// ---------------- per-node scalars: sS=he.a_src, sD=he.a_dst, pD=hr.a_dif ---
__global__ void node_scalar(const float* __restrict__ a) {
    int gw = (blockIdx.x * blockDim.x + threadIdx.x) >> 5;
    int lane = threadIdx.x & 31;
    if (gw >= NN * HH) return;
    int n = gw >> 3, h = gw & 7;
    const float* he = g_he + n * HD + h * DD;
    const float* hr = g_hr + n * HD + h * DD;
    const float* ah = a + h * (5 * DD);

    float s1 = he[lane] * ah[lane] + he[lane + 32] * ah[lane + 32];
    float s2 = he[lane] * ah[DD + lane] + he[lane + 32] * ah[DD + lane + 32];
    float s3 = hr[lane] * ah[2 * DD + lane] + hr[lane + 32] * ah[2 * DD + lane + 32];
#pragma unroll
    for (int o = 16; o; o >>= 1) {
        s1 += __shfl_xor_sync(0xffffffffu, s1, o);
        s2 += __shfl_xor_sync(0xffffffffu, s2, o);
        s3 += __shfl_xor_sync(0xffffffffu, s3, o);
    }
    if (lane == 0) {
        g_sS[n * HH + h] = s1;
        g_sD[n * HH + h] = s2;
        g_pD[n * HH + h] = s3;
    }
}

// ---------------- CSR build ----------------
__global__ void zero_deg() {
    int i = blockIdx.x * blockDim.x + threadIdx.x;
    if (i < NN) g_deg[i] = 0;
}

__global__ void hist_k(const void* __restrict__ ei) {
    int e = blockIdx.x * blockDim.x + threadIdx.x;
    if (e >= EE) return;
    int s = load_idx(ei, 0, e);
    atomicAdd(&g_deg[s], 1);
}

__global__ void scan_k() {
    __shared__ int sbuf[1024];
    __shared__ int carry_s;
    int tid = threadIdx.x;
    if (tid == 0) carry_s = 0;
    __syncthreads();
    for (int base = 0; base < NN; base += 1024) {
        int i = base + tid;
        int v = (i < NN) ? g_deg[i] : 0;
        sbuf[tid] = v;
        __syncthreads();
        for (int o = 1; o < 1024; o <<= 1) {
            int t = (tid >= o) ? sbuf[tid - o] : 0;
            __syncthreads();
            sbuf[tid] += t;
            __syncthreads();
        }
        int incl = sbuf[tid];
        int c = carry_s;
        __syncthreads();
        if (i < NN) g_off[i + 1] = c + incl;
        if (tid == 1023) carry_s = c + incl;
        __syncthreads();
    }
    if (tid == 0) g_off[0] = 0;
}

__global__ void copy_cur() {
    int i = blockIdx.x * blockDim.x + threadIdx.x;
    if (i < NN) g_cur[i] = g_off[i];
}

__global__ void scatter_k(const void* __restrict__ ei) {
    int e = blockIdx.x * blockDim.x + threadIdx.x;
    if (e >= EE) return;
    int s = load_idx(ei, 0, e);
    int t = load_idx(ei, 1, e);
    int p = atomicAdd(&g_cur[s], 1);
    g_srcs[p] = s;
    g_dsts[p] = t;
}

// ---------------- per-edge scores (warp per edge, all 8 heads) --------------
__global__ __launch_bounds__(256) void score_k(const float* __restrict__ a) {
    __shared__ float sAbs[HD], sPrd[HD];
    int tid = threadIdx.x;
    for (int i = tid; i < HD; i += 256) {
        int h = i >> 6, d = i & 63;
        sAbs[i] = a[h * 320 + 3 * DD + d];
        sPrd[i] = a[h * 320 + 4 * DD + d];
    }
    __syncthreads();

    int p = blockIdx.x * 8 + (tid >> 5);
    int lane = tid & 31;
    if (p >= EE) return;
    int s = g_srcs[p], t = g_dsts[p];
    const float* rs = g_hr + (long)s * HD;
    const float* rt = g_hr + (long)t * HD;

    float accA[8], accP[8];
#pragma unroll
    for (int h = 0; h < 8; h++) { accA[h] = 0.f; accP[h] = 0.f; }

#pragma unroll
    for (int k = 0; k < 16; k++) {
        int i = lane + 32 * k;
        float vs = rs[i], vt = rt[i];
        float df = vt - vs;
        int h = k >> 1;      // compile-time per unrolled iter
        accA[h] = fmaf(sAbs[i], fabsf(df), accA[h]);
        accP[h] = fmaf(sPrd[i] * vs, vt, accP[h]);
    }

    float myA = 0.f, myP = 0.f;
#pragma unroll
    for (int h = 0; h < 8; h++) {
        float va = accA[h], vp = accP[h];
#pragma unroll
        for (int o = 16; o; o >>= 1) {
            va += __shfl_xor_sync(0xffffffffu, va, o);
            vp += __shfl_xor_sync(0xffffffffu, vp, o);
        }
        if (lane == h) { myA = va; myP = vp; }
    }

    if (lane < 8) {
        int h = lane;
        float sc = g_sS[s * HH + h] + g_sD[t * HH + h] + g_pD[t * HH + h] - g_pD[s * HH + h] + myA + myP;
        float al = sc > 0.f ? sc : LRELU * sc;
        g_att[h * EE + p] = al;
    }
}

// ---------------- segment softmax over src (warp per node) ------------------
__global__ void softmax_k() {
    int w = (blockIdx.x * blockDim.x + threadIdx.x) >> 5;
    int lane = threadIdx.x & 31;
    if (w >= NN) return;
    int beg = g_off[w], end = g_off[w + 1];
    if (beg == end) return;
#pragma unroll
    for (int h = 0; h < 8; h++) {
        float* arr = g_att + (long)h * EE;
        float m = -3.4e38f;
        for (int j = beg + lane; j < end; j += 32) m = fmaxf(m, arr[j]);
#pragma unroll
        for (int o = 16; o; o >>= 1) m = fmaxf(m, __shfl_xor_sync(0xffffffffu, m, o));
        float sum = 0.f;
        for (int j = beg + lane; j < end; j += 32) {
            float e = expf(arr[j] - m);
            arr[j] = e;
            sum += e;
        }
#pragma unroll
        for (int o = 16; o; o >>= 1) sum += __shfl_xor_sync(0xffffffffu, sum, o);
        float inv = 1.f / (sum + EPSV);
        for (int j = beg + lane; j < end; j += 32) arr[j] *= inv;
    }
}

// ---------------- aggregation (block per node, no atomics) ------------------
__global__ __launch_bounds__(128) void agg_k(float* __restrict__ out) {
    int n = blockIdx.x;
    int tid = threadIdx.x;
    int beg = g_off[n], end = g_off[n + 1];
    float acc0 = 0.f, acc1 = 0.f, acc2 = 0.f, acc3 = 0.f;
    int h0 = (tid) >> 6;
    int h1 = (tid + 128) >> 6;
    int h2 = (tid + 256) >> 6;
    int h3 = (tid + 384) >> 6;
    for (int p = beg; p < end; p++) {
        int t = g_dsts[p];
        const float* he = g_he + (long)t * HD;
        float a0 = g_att[(long)h0 * EE + p];
        float a1 = g_att[(long)h1 * EE + p];
        float a2 = g_att[(long)h2 * EE + p];
        float a3 = g_att[(long)h3 * EE + p];
        acc0 = fmaf(a0, he[tid], acc0);
        acc1 = fmaf(a1, he[tid + 128], acc1);
        acc2 = fmaf(a2, he[tid + 256], acc2);
        acc3 = fmaf(a3, he[tid + 384], acc3);
    }
    float* o = out + (long)n * HD;
    o[tid] = acc0;
    o[tid + 128] = acc1;
    o[tid + 256] = acc2;
    o[tid + 384] = acc3;
}

// ---------------- launch ----------------
extern "C" void kernel_launch(void* const* d_in, const int* in_sizes, int n_in,
                              void* d_out, int out_size) {
    const float* x  = (const float*)d_in[0];
    const void*  ei = d_in[1];
    const float* We = (const float*)d_in[2];
    const float* Wr = (const float*)d_in[3];
    const float* a  = (const float*)d_in[4];
    float* out = (float*)d_out;

    detect_k<<<1, 32>>>((const int*)ei);

    prep_w<<<(2 * FF * HD + 255) / 256, 256>>>(We, Wr);

    dim3 gg((NN + 127) / 128, HD / 128, 2);
    sgemm<<<gg, 256>>>(x);

    node_scalar<<<(NN * HH * 32 + 255) / 256, 256>>>(a);

    zero_deg<<<(NN + 255) / 256, 256>>>();
    hist_k<<<(EE + 255) / 256, 256>>>(ei);
    scan_k<<<1, 1024>>>();
    copy_cur<<<(NN + 255) / 256, 256>>>();
    scatter_k<<<(EE + 255) / 256, 256>>>(ei);

    score_k<<<(EE + 7) / 8, 256>>>(a);
    softmax_k<<<(NN * 32 + 255) / 256, 256>>>();
    agg_k<<<NN, 128>>>(out);
}

// round 9
// speedup vs baseline: 1.5976x; 1.5976x over previous
#include <cuda_runtime.h>
#include <cuda_bf16.h>
#include <cstdint>

#define NN 20000
#define EE 320000
#define FF 512
#define HH 8
#define DD 64
#define HD 512           // HH*DD
#define LRELU 0.2f
#define EPSV 1e-16f

#define TM 128
#define TN 128
#define A_BYTES 16384            // 128 rows x 64 bf16 (128B)
#define STAGE_BYTES 32768        // A tile + B tile
#define NSTAGE 24                // 8 K-chunks x 3 hi/lo combos

// ---------------- scratch (static device globals; no allocs) ----------------
__device__ float g_he[NN * HD];
__device__ float g_hr[NN * HD];
__device__ __nv_bfloat16 g_xh[NN * FF];
__device__ __nv_bfloat16 g_xl[NN * FF];
__device__ __nv_bfloat16 g_Wbh[2][FF * HD];   // [mat][n][k]  (n = h*64+d, k = f)
__device__ __nv_bfloat16 g_Wbl[2][FF * HD];
__device__ float g_sS[NN * HH];
__device__ float g_sD[NN * HH];
__device__ float g_pD[NN * HH];
__device__ int   g_deg[NN];
__device__ int   g_off[NN + 1];
__device__ int   g_cur[NN];
__device__ int   g_srcs[EE];
__device__ int   g_dsts[EE];
__device__ float g_att[HH * EE];
__device__ int   g_is64;

// ---------------- small helpers ----------------
__device__ __forceinline__ uint32_t smem_u32(const void* p) {
    uint32_t a;
    asm("{ .reg .u64 t; cvta.to.shared.u64 t, %1; cvt.u32.u64 %0, t; }" : "=r"(a) : "l"(p));
    return a;
}

__device__ __forceinline__ void cp16(uint32_t dst, const void* src, int srcsize) {
    asm volatile("cp.async.cg.shared.global [%0], [%1], 16, %2;"
                 :: "r"(dst), "l"(src), "r"(srcsize) : "memory");
}

#define SWZ(o) ((o) ^ (((o) >> 3) & 0x70))

#define LDSM4(r, a) \
    asm volatile("ldmatrix.sync.aligned.m8n8.x4.shared.b16 {%0,%1,%2,%3}, [%4];" \
                 : "=r"((r)[0]), "=r"((r)[1]), "=r"((r)[2]), "=r"((r)[3]) : "r"(a))

#define MMA16816(c, a, b0, b1) \
    asm volatile("mma.sync.aligned.m16n8k16.row.col.f32.bf16.bf16.f32 " \
                 "{%0,%1,%2,%3},{%4,%5,%6,%7},{%8,%9},{%0,%1,%2,%3};" \
                 : "+f"((c)[0]), "+f"((c)[1]), "+f"((c)[2]), "+f"((c)[3]) \
                 : "r"((a)[0]), "r"((a)[1]), "r"((a)[2]), "r"((a)[3]), \
                   "r"(b0), "r"(b1))

// ---------------- dtype probe ----------------
__global__ void detect_k(const int* __restrict__ w) {
    if (threadIdx.x == 0 && blockIdx.x == 0) {
        int ornz = 0;
        for (int i = 1; i < 256; i += 2) ornz |= w[i];
        g_is64 = (ornz == 0) ? 1 : 0;
    }
}

__device__ __forceinline__ int load_idx(const void* ei, int which, int e) {
    if (g_is64) return (int)((const long long*)ei)[(long)which * EE + e];
    return ((const int*)ei)[which * EE + e];
}

// ---------------- x -> bf16 hi/lo ----------------
__global__ void cvt_x(const float* __restrict__ x) {
    int i = blockIdx.x * blockDim.x + threadIdx.x;
    if (i >= NN * FF / 4) return;
    float4 v = ((const float4*)x)[i];
    __nv_bfloat16 h0 = __float2bfloat16_rn(v.x);
    __nv_bfloat16 h1 = __float2bfloat16_rn(v.y);
    __nv_bfloat16 h2 = __float2bfloat16_rn(v.z);
    __nv_bfloat16 h3 = __float2bfloat16_rn(v.w);
    __nv_bfloat16 l0 = __float2bfloat16_rn(v.x - __bfloat162float(h0));
    __nv_bfloat16 l1 = __float2bfloat16_rn(v.y - __bfloat162float(h1));
    __nv_bfloat16 l2 = __float2bfloat16_rn(v.z - __bfloat162float(h2));
    __nv_bfloat16 l3 = __float2bfloat16_rn(v.w - __bfloat162float(h3));
    ((__nv_bfloat162*)g_xh)[i * 2 + 0] = __nv_bfloat162(h0, h1);
    ((__nv_bfloat162*)g_xh)[i * 2 + 1] = __nv_bfloat162(h2, h3);
    ((__nv_bfloat162*)g_xl)[i * 2 + 0] = __nv_bfloat162(l0, l1);
    ((__nv_bfloat162*)g_xl)[i * 2 + 1] = __nv_bfloat162(l2, l3);
}

// ---------------- W -> bf16 hi/lo, transposed to [n][k] ---------------------
__global__ void prep_wb(const float* __restrict__ We, const float* __restrict__ Wr) {
    int idx = blockIdx.x * blockDim.x + threadIdx.x;
    if (idx >= 2 * FF * HD) return;
    int which = idx / (FF * HD);
    int rem = idx - which * (FF * HD);
    int n = rem >> 9;        // output column = h*64+d
    int k = rem & 511;       // input feature f
    int h = n >> 6, d = n & 63;
    const float* W = which ? Wr : We;
    float v = W[h * (FF * DD) + k * DD + d];
    __nv_bfloat16 hi = __float2bfloat16_rn(v);
    __nv_bfloat16 lo = __float2bfloat16_rn(v - __bfloat162float(hi));
    g_Wbh[which][n * FF + k] = hi;
    g_Wbl[which][n * FF + k] = lo;
}

// ---------------- stage loader: A 128x64bf16 + B 128x64bf16, SW128 ----------
__device__ __forceinline__ void load_stage(int s, int tid, int mBase, int nBase,
                                           uint32_t smem_base,
                                           const __nv_bfloat16* Wh,
                                           const __nv_bfloat16* Wl) {
    int combo = s >> 3, kc = s & 7;
    const __nv_bfloat16* Asrc = (combo < 2) ? g_xh : g_xl;
    const __nv_bfloat16* Bsrc = (combo == 1) ? Wl : Wh;
    uint32_t abase = smem_base + (s % 3) * STAGE_BYTES;
    uint32_t bbase = abase + A_BYTES;
#pragma unroll
    for (int i = tid; i < 1024; i += 256) {
        int row = i >> 3, c = i & 7;
        int gm = mBase + row;
        uint32_t dst = abase + SWZ(row * 128 + c * 16);
        size_t off = (gm < NN) ? ((size_t)gm * 1024 + kc * 128 + c * 16) : 0;
        cp16(dst, (const char*)Asrc + off, gm < NN ? 16 : 0);
    }
#pragma unroll
    for (int i = tid; i < 1024; i += 256) {
        int row = i >> 3, c = i & 7;
        int n = nBase + row;
        uint32_t dst = bbase + SWZ(row * 128 + c * 16);
        cp16(dst, (const char*)Bsrc + ((size_t)n * 1024 + kc * 128 + c * 16), 16);
    }
    asm volatile("cp.async.commit_group;" ::: "memory");
}

// ---------------- bf16 mma.sync GEMM: C = xh*Wh + xh*Wl + xl*Wh -------------
__global__ __launch_bounds__(256, 1) void mma_k() {
    extern __shared__ char smem[];
    int tid = threadIdx.x, wid = tid >> 5, lane = tid & 31;
    int mBase = blockIdx.x * TM;
    int nBase = blockIdx.y * TN;
    int mat = blockIdx.z;
    const __nv_bfloat16* Wh = g_Wbh[mat];
    const __nv_bfloat16* Wl = g_Wbl[mat];
    float* C = mat ? g_hr : g_he;

    uint32_t smem_base = smem_u32(smem);

    int warp_m = wid >> 2;          // 0..1  -> m offset *64
    int warp_n = wid & 3;           // 0..3  -> n offset *32
    int g = lane >> 3, lr = lane & 7;

    // ldmatrix per-lane source coords (within tile)
    int arow = warp_m * 64 + (g & 1) * 8 + lr;     // + im*16
    int abyt = (g >> 1) * 16;                      // + ks*32
    int brow = warp_n * 32 + (g >> 1) * 8 + lr;    // + jp*16
    int bbyt = (g & 1) * 16;                       // + ks*32

    float acc[16][4];
#pragma unroll
    for (int i = 0; i < 16; i++)
#pragma unroll
        for (int j = 0; j < 4; j++) acc[i][j] = 0.f;

    load_stage(0, tid, mBase, nBase, smem_base, Wh, Wl);
    load_stage(1, tid, mBase, nBase, smem_base, Wh, Wl);
    load_stage(2, tid, mBase, nBase, smem_base, Wh, Wl);

    for (int s = 0; s < NSTAGE; s++) {
        if (s <= NSTAGE - 3)      asm volatile("cp.async.wait_group 2;" ::: "memory");
        else if (s == NSTAGE - 2) asm volatile("cp.async.wait_group 1;" ::: "memory");
        else                      asm volatile("cp.async.wait_group 0;" ::: "memory");
        __syncthreads();

        uint32_t abase = smem_base + (s % 3) * STAGE_BYTES;
        uint32_t bbase = abase + A_BYTES;

#pragma unroll
        for (int ks = 0; ks < 4; ks++) {
            uint32_t af[4][4], bf[2][4];
#pragma unroll
            for (int im = 0; im < 4; im++) {
                uint32_t a = abase + SWZ((arow + im * 16) * 128 + ks * 32 + abyt);
                LDSM4(af[im], a);
            }
#pragma unroll
            for (int jp = 0; jp < 2; jp++) {
                uint32_t b = bbase + SWZ((brow + jp * 16) * 128 + ks * 32 + bbyt);
                LDSM4(bf[jp], b);
            }
#pragma unroll
            for (int im = 0; im < 4; im++) {
#pragma unroll
                for (int jn = 0; jn < 4; jn++) {
                    uint32_t b0 = bf[jn >> 1][(jn & 1) * 2 + 0];
                    uint32_t b1 = bf[jn >> 1][(jn & 1) * 2 + 1];
                    MMA16816(acc[im * 4 + jn], af[im], b0, b1);
                }
            }
        }
        __syncthreads();   // everyone done reading buffer s%3 before refill

        int t = s + 3;
        if (t < NSTAGE) load_stage(t, tid, mBase, nBase, smem_base, Wh, Wl);
    }

    // epilogue
    int q = lane >> 2, rpair = lane & 3;
#pragma unroll
    for (int im = 0; im < 4; im++) {
        int r0 = mBase + warp_m * 64 + im * 16 + q;
        int r1 = r0 + 8;
#pragma unroll
        for (int jn = 0; jn < 4; jn++) {
            int col = nBase + warp_n * 32 + jn * 8 + rpair * 2;
            float* c = acc[im * 4 + jn];
            if (r0 < NN) *(float2*)(C + (size_t)r0 * HD + col) = make_float2(c[0], c[1]);
            if (r1 < NN) *(float2*)(C + (size_t)r1 * HD + col) = make_float2(c[2], c[3]);
        }
    }
}

// ---------------- per-node scalars ----------------
__global__ void node_scalar(const float* __restrict__ a) {
    int gw = (blockIdx.x * blockDim.x + threadIdx.x) >> 5;
    int lane = threadIdx.x & 31;
    if (gw >= NN * HH) return;
    int n = gw >> 3, h = gw & 7;
    const float* he = g_he + n * HD + h * DD;
    const float* hr = g_hr + n * HD + h * DD;
    const float* ah = a + h * (5 * DD);

    float s1 = he[lane] * ah[lane] + he[lane + 32] * ah[lane + 32];
    float s2 = he[lane] * ah[DD + lane] + he[lane + 32] * ah[DD + lane + 32];
    float s3 = hr[lane] * ah[2 * DD + lane] + hr[lane + 32] * ah[2 * DD + lane + 32];
#pragma unroll
    for (int o = 16; o; o >>= 1) {
        s1 += __shfl_xor_sync(0xffffffffu, s1, o);
        s2 += __shfl_xor_sync(0xffffffffu, s2, o);
        s3 += __shfl_xor_sync(0xffffffffu, s3, o);
    }
    if (lane == 0) {
        g_sS[n * HH + h] = s1;
        g_sD[n * HH + h] = s2;
        g_pD[n * HH + h] = s3;
    }
}

// ---------------- CSR build ----------------
__global__ void zero_deg() {
    int i = blockIdx.x * blockDim.x + threadIdx.x;
    if (i < NN) g_deg[i] = 0;
}

__global__ void hist_k(const void* __restrict__ ei) {
    int e = blockIdx.x * blockDim.x + threadIdx.x;
    if (e >= EE) return;
    atomicAdd(&g_deg[load_idx(ei, 0, e)], 1);
}

__global__ void scan_k() {
    __shared__ int sbuf[1024];
    __shared__ int carry_s;
    int tid = threadIdx.x;
    if (tid == 0) carry_s = 0;
    __syncthreads();
    for (int base = 0; base < NN; base += 1024) {
        int i = base + tid;
        int v = (i < NN) ? g_deg[i] : 0;
        sbuf[tid] = v;
        __syncthreads();
        for (int o = 1; o < 1024; o <<= 1) {
            int t = (tid >= o) ? sbuf[tid - o] : 0;
            __syncthreads();
            sbuf[tid] += t;
            __syncthreads();
        }
        int incl = sbuf[tid];
        int c = carry_s;
        __syncthreads();
        if (i < NN) g_off[i + 1] = c + incl;
        if (tid == 1023) carry_s = c + incl;
        __syncthreads();
    }
    if (tid == 0) g_off[0] = 0;
}

__global__ void copy_cur() {
    int i = blockIdx.x * blockDim.x + threadIdx.x;
    if (i < NN) g_cur[i] = g_off[i];
}

__global__ void scatter_k(const void* __restrict__ ei) {
    int e = blockIdx.x * blockDim.x + threadIdx.x;
    if (e >= EE) return;
    int s = load_idx(ei, 0, e);
    int t = load_idx(ei, 1, e);
    int p = atomicAdd(&g_cur[s], 1);
    g_srcs[p] = s;
    g_dsts[p] = t;
}

// ---------------- per-edge scores ----------------
__global__ __launch_bounds__(256) void score_k(const float* __restrict__ a) {
    __shared__ float sAbs[HD], sPrd[HD];
    int tid = threadIdx.x;
    for (int i = tid; i < HD; i += 256) {
        int h = i >> 6, d = i & 63;
        sAbs[i] = a[h * 320 + 3 * DD + d];
        sPrd[i] = a[h * 320 + 4 * DD + d];
    }
    __syncthreads();

    int p = blockIdx.x * 8 + (tid >> 5);
    int lane = tid & 31;
    if (p >= EE) return;
    int s = g_srcs[p], t = g_dsts[p];
    const float* rs = g_hr + (long)s * HD;
    const float* rt = g_hr + (long)t * HD;

    float accA[8], accP[8];
#pragma unroll
    for (int h = 0; h < 8; h++) { accA[h] = 0.f; accP[h] = 0.f; }

#pragma unroll
    for (int k = 0; k < 16; k++) {
        int i = lane + 32 * k;
        float vs = rs[i], vt = rt[i];
        float df = vt - vs;
        int h = k >> 1;
        accA[h] = fmaf(sAbs[i], fabsf(df), accA[h]);
        accP[h] = fmaf(sPrd[i] * vs, vt, accP[h]);
    }

    float myA = 0.f, myP = 0.f;
#pragma unroll
    for (int h = 0; h < 8; h++) {
        float va = accA[h], vp = accP[h];
#pragma unroll
        for (int o = 16; o; o >>= 1) {
            va += __shfl_xor_sync(0xffffffffu, va, o);
            vp += __shfl_xor_sync(0xffffffffu, vp, o);
        }
        if (lane == h) { myA = va; myP = vp; }
    }

    if (lane < 8) {
        int h = lane;
        float sc = g_sS[s * HH + h] + g_sD[t * HH + h] + g_pD[t * HH + h] - g_pD[s * HH + h] + myA + myP;
        float al = sc > 0.f ? sc : LRELU * sc;
        g_att[h * EE + p] = al;
    }
}

// ---------------- segment softmax ----------------
__global__ void softmax_k() {
    int w = (blockIdx.x * blockDim.x + threadIdx.x) >> 5;
    int lane = threadIdx.x & 31;
    if (w >= NN) return;
    int beg = g_off[w], end = g_off[w + 1];
    if (beg == end) return;
#pragma unroll
    for (int h = 0; h < 8; h++) {
        float* arr = g_att + (long)h * EE;
        float m = -3.4e38f;
        for (int j = beg + lane; j < end; j += 32) m = fmaxf(m, arr[j]);
#pragma unroll
        for (int o = 16; o; o >>= 1) m = fmaxf(m, __shfl_xor_sync(0xffffffffu, m, o));
        float sum = 0.f;
        for (int j = beg + lane; j < end; j += 32) {
            float e = expf(arr[j] - m);
            arr[j] = e;
            sum += e;
        }
#pragma unroll
        for (int o = 16; o; o >>= 1) sum += __shfl_xor_sync(0xffffffffu, sum, o);
        float inv = 1.f / (sum + EPSV);
        for (int j = beg + lane; j < end; j += 32) arr[j] *= inv;
    }
}

// ---------------- aggregation ----------------
__global__ __launch_bounds__(128) void agg_k(float* __restrict__ out) {
    int n = blockIdx.x;
    int tid = threadIdx.x;
    int beg = g_off[n], end = g_off[n + 1];
    float acc0 = 0.f, acc1 = 0.f, acc2 = 0.f, acc3 = 0.f;
    int h0 = (tid) >> 6;
    int h1 = (tid + 128) >> 6;
    int h2 = (tid + 256) >> 6;
    int h3 = (tid + 384) >> 6;
    for (int p = beg; p < end; p++) {
        int t = g_dsts[p];
        const float* he = g_he + (long)t * HD;
        float a0 = g_att[(long)h0 * EE + p];
        float a1 = g_att[(long)h1 * EE + p];
        float a2 = g_att[(long)h2 * EE + p];
        float a3 = g_att[(long)h3 * EE + p];
        acc0 = fmaf(a0, he[tid], acc0);
        acc1 = fmaf(a1, he[tid + 128], acc1);
        acc2 = fmaf(a2, he[tid + 256], acc2);
        acc3 = fmaf(a3, he[tid + 384], acc3);
    }
    float* o = out + (long)n * HD;
    o[tid] = acc0;
    o[tid + 128] = acc1;
    o[tid + 256] = acc2;
    o[tid + 384] = acc3;
}

// ---------------- launch ----------------
extern "C" void kernel_launch(void* const* d_in, const int* in_sizes, int n_in,
                              void* d_out, int out_size) {
    const float* x  = (const float*)d_in[0];
    const void*  ei = d_in[1];
    const float* We = (const float*)d_in[2];
    const float* Wr = (const float*)d_in[3];
    const float* a  = (const float*)d_in[4];
    float* out = (float*)d_out;

    static int smem_set = 0;
    if (!smem_set) {
        cudaFuncSetAttribute(mma_k, cudaFuncAttributeMaxDynamicSharedMemorySize,
                             3 * STAGE_BYTES);
        smem_set = 1;
    }

    detect_k<<<1, 32>>>((const int*)ei);
    prep_wb<<<(2 * FF * HD + 255) / 256, 256>>>(We, Wr);
    cvt_x<<<(NN * FF / 4 + 255) / 256, 256>>>(x);

    dim3 gg((NN + TM - 1) / TM, HD / TN, 2);
    mma_k<<<gg, 256, 3 * STAGE_BYTES>>>();

    node_scalar<<<(NN * HH * 32 + 255) / 256, 256>>>(a);

    zero_deg<<<(NN + 255) / 256, 256>>>();
    hist_k<<<(EE + 255) / 256, 256>>>(ei);
    scan_k<<<1, 1024>>>();
    copy_cur<<<(NN + 255) / 256, 256>>>();
    scatter_k<<<(EE + 255) / 256, 256>>>(ei);

    score_k<<<(EE + 7) / 8, 256>>>(a);
    softmax_k<<<(NN * 32 + 255) / 256, 256>>>();
    agg_k<<<NN, 128>>>(out);
}